// round 8
// baseline (speedup 1.0000x reference)
#include <cuda_runtime.h>
#include <math.h>
#include <stdint.h>

#define N_REGIONS 10
#define HIDDEN    128
#define HEADS     4
#define N_LAYERS  3
#define CHPR      7
#define TOKENS    16384
#define TW        12                         // tokens per CTA
#define NCTAS     ((TOKENS + TW - 1) / TW)   // 1366
#define NT        256                        // 8 warps

typedef unsigned long long u64;
typedef uint32_t u32;

__constant__ int c_nbr_cnt[N_REGIONS] = {5,5,5,3,3,4,3,4,2,2};
__constant__ int c_nbr[N_REGIONS][5] = {
    {0,1,2,3,4},{0,1,2,5,7},{0,1,2,3,7},{0,2,3,0,0},{0,4,5,0,0},
    {1,4,5,6,0},{5,6,9,0,0},{1,2,7,8,0},{7,8,0,0,0},{6,9,0,0,0}
};

// fragment-major packed W (tf32 bits): idx = ((l*4+h)*256 + kt*16 + nt)*32 + lane
// tf32 m16n8k8 B layout (col-major KxN): b0 = W[k=kt*8+tq][e=nt*8+g], b1 = W[k=kt*8+tq+4][e]
__device__ u64 g_Wpack[N_LAYERS * HEADS * 16 * 16 * 32];

__device__ __forceinline__ float gelu_exact(float v) {
    return 0.5f * v * (1.0f + erff(v * 0.70710678118654752f));
}
__device__ __forceinline__ u32 cvt_tf32(float f) {
    u32 r; asm("cvt.rna.tf32.f32 %0, %1;" : "=r"(r) : "f"(f)); return r;
}
__device__ __forceinline__ void mma_tf32(float c[4], const u32 a[4], u32 b0, u32 b1) {
    asm volatile(
        "mma.sync.aligned.m16n8k8.row.col.f32.tf32.tf32.f32 "
        "{%0,%1,%2,%3}, {%4,%5,%6,%7}, {%8,%9}, {%0,%1,%2,%3};"
        : "+f"(c[0]), "+f"(c[1]), "+f"(c[2]), "+f"(c[3])
        : "r"(a[0]), "r"(a[1]), "r"(a[2]), "r"(a[3]), "r"(b0), "r"(b1));
}

// ---------- one-off: W_gat (L,128,4,128) -> fragment-major packed tf32 ----------
__global__ void wpack_kernel(const float* __restrict__ W) {
    const int idx  = blockIdx.x * 256 + threadIdx.x;   // 98304 total
    const int lane = idx & 31;
    const int nt   = (idx >> 5) & 15;
    const int kt   = (idx >> 9) & 15;
    const int h    = (idx >> 13) & 3;
    const int l    = idx >> 15;
    const int tq = lane & 3, g = lane >> 2;
    const int k0 = kt * 8 + tq;          // tf32 B: k = tq and tq+4
    const int e  = nt * 8 + g;
    const u32 b0 = cvt_tf32(W[((size_t)(l * 128 + k0)     * 4 + h) * 128 + e]);
    const u32 b1 = cvt_tf32(W[((size_t)(l * 128 + k0 + 4) * 4 + h) * 128 + e]);
    g_Wpack[idx] = ((u64)b1 << 32) | (u64)b0;
}

// ---------- smem ----------
struct Smem {
    float nodes[128][132];      // A matrix (rows 120..127 zero pad)
    float hh[128][132];         // per-head GEMM result
    float outacc[120][132];     // per-layer head-mean accumulator
    float alpha[TW * 10 * 10];  // [tt][i][j]
    float as[128], ad[128];
    float xs[TW * 70];
    float mu[120], rstd[120];
};

__global__ void __launch_bounds__(NT, 1) brain_mma_kernel(
    const float* __restrict__ x,
    const float* __restrict__ W_enc,
    const float* __restrict__ b_enc,
    const float* __restrict__ g_enc,
    const float* __restrict__ beta_enc,
    const float* __restrict__ att_src,
    const float* __restrict__ att_dst,
    const float* __restrict__ b_gat,
    float* __restrict__ out)
{
    extern __shared__ Smem S[];
    const int t    = threadIdx.x;
    const int w    = t >> 5;
    const int lane = t & 31;
    const int g    = lane >> 2;
    const int tq   = lane & 3;
    const int tok0 = blockIdx.x * TW;
    const int e    = t & 127;            // feature column for elementwise phases

    // ---- zero pad rows of A, load token inputs ----
    for (int i = t; i < 8 * 132; i += NT) S->nodes[120 + i / 132][i % 132] = 0.0f;
    for (int i = t; i < TW * 70; i += NT) {
        const int tt = i / 70, tok = tok0 + tt;
        S->xs[i] = (tok < TOKENS) ? x[(size_t)tok * 70 + (i - tt * 70)] : 0.0f;
    }
    __syncthreads();

    // ---- encoder Linear(7,128): rows = tt*10+r ----
    {
        const int th = t >> 7;
        #pragma unroll 1
        for (int r = 0; r < N_REGIONS; r++) {
            float wv[CHPR];
            #pragma unroll
            for (int c = 0; c < CHPR; c++) wv[c] = W_enc[(r * CHPR + c) * 128 + e];
            const float bb = b_enc[r * 128 + e];
            #pragma unroll
            for (int q = 0; q < 6; q++) {
                const int tt = th + 2 * q;
                float acc = bb;
                #pragma unroll
                for (int c = 0; c < CHPR; c++)
                    acc += S->xs[tt * 70 + r * CHPR + c] * wv[c];
                S->nodes[tt * 10 + r][e] = acc;
            }
        }
    }
    __syncthreads();

    // ---- LayerNorm stats (rows 0..119 over 8 warps) ----
    for (int row = w; row < 120; row += 8) {
        float v0 = S->nodes[row][lane];
        float v1 = S->nodes[row][lane + 32];
        float v2 = S->nodes[row][lane + 64];
        float v3 = S->nodes[row][lane + 96];
        float s  = v0 + v1 + v2 + v3;
        float sq = v0 * v0 + v1 * v1 + v2 * v2 + v3 * v3;
        #pragma unroll
        for (int o = 16; o > 0; o >>= 1) {
            s  += __shfl_xor_sync(0xffffffffu, s, o);
            sq += __shfl_xor_sync(0xffffffffu, sq, o);
        }
        if (lane == 0) {
            const float m = s * (1.0f / 128.0f);
            S->mu[row]   = m;
            S->rstd[row] = rsqrtf(sq * (1.0f / 128.0f) - m * m + 1e-5f);
        }
    }
    __syncthreads();

    // ---- LN affine + GELU -> nodes + enc output ----
    #pragma unroll
    for (int q = 0; q < 6; q++) {
        const int p = t + NT * q;
        const int tt = p >> 7;
        const int tok = tok0 + tt;
        #pragma unroll
        for (int r = 0; r < N_REGIONS; r++) {
            const int row = tt * 10 + r;
            float v = (S->nodes[row][e] - S->mu[row]) * S->rstd[row]
                      * g_enc[r * 128 + e] + beta_enc[r * 128 + e];
            const float gv = gelu_exact(v);
            S->nodes[row][e] = gv;
            if (tok < TOKENS)
                out[(size_t)TOKENS * 1280 + (size_t)tok * 1280 + r * 128 + e] = gv;
        }
    }
    __syncthreads();

    // ---- GAT layers ----
    #pragma unroll 1
    for (int l = 0; l < N_LAYERS; l++) {
        // load A fragments for this layer (warp strip rows [16w,16w+16))
        // tf32 m16n8k8 A layout: a0=(g,tq) a1=(g+8,tq) a2=(g,tq+4) a3=(g+8,tq+4)
        u32 afr[16][4];
        {
            const int r0 = w * 16 + g;
            #pragma unroll
            for (int kt = 0; kt < 16; kt++) {
                afr[kt][0] = cvt_tf32(S->nodes[r0]    [kt * 8 + tq]);
                afr[kt][1] = cvt_tf32(S->nodes[r0 + 8][kt * 8 + tq]);
                afr[kt][2] = cvt_tf32(S->nodes[r0]    [kt * 8 + tq + 4]);
                afr[kt][3] = cvt_tf32(S->nodes[r0 + 8][kt * 8 + tq + 4]);
            }
        }

        #pragma unroll 1
        for (int h = 0; h < HEADS; h++) {
            // ---- MMA: hh = nodes x W_{l,h}  (M=128 strip/warp, N=128, K=128) ----
            {
                const u64* __restrict__ bp = g_Wpack + (size_t)((l * 4 + h) * 256) * 32 + lane;
                #pragma unroll 1
                for (int ng = 0; ng < 4; ng++) {        // 4 n-tiles per group
                    float acc[4][4];
                    #pragma unroll
                    for (int j = 0; j < 4; j++)
                        #pragma unroll
                        for (int i2 = 0; i2 < 4; i2++) acc[j][i2] = 0.0f;
                    #pragma unroll
                    for (int kt = 0; kt < 16; kt++) {
                        u64 bw[4];
                        #pragma unroll
                        for (int j = 0; j < 4; j++)
                            bw[j] = __ldg(bp + (size_t)(kt * 16 + ng * 4 + j) * 32);
                        #pragma unroll
                        for (int j = 0; j < 4; j++)
                            mma_tf32(acc[j], afr[kt], (u32)bw[j], (u32)(bw[j] >> 32));
                    }
                    const int r0 = w * 16 + g;
                    #pragma unroll
                    for (int j = 0; j < 4; j++) {
                        const int col = (ng * 4 + j) * 8 + 2 * tq;   // C layout: (g, 2tq),(g,2tq+1)
                        *reinterpret_cast<float2*>(&S->hh[r0][col])     = make_float2(acc[j][0], acc[j][1]);
                        *reinterpret_cast<float2*>(&S->hh[r0 + 8][col]) = make_float2(acc[j][2], acc[j][3]);
                    }
                }
            }
            __syncthreads();

            // ---- attention dots: as/ad per row ----
            {
                float s0 = __ldg(att_src + (l * 4 + h) * 128 + lane);
                float s1 = __ldg(att_src + (l * 4 + h) * 128 + lane + 32);
                float s2 = __ldg(att_src + (l * 4 + h) * 128 + lane + 64);
                float s3 = __ldg(att_src + (l * 4 + h) * 128 + lane + 96);
                float d0 = __ldg(att_dst + (l * 4 + h) * 128 + lane);
                float d1 = __ldg(att_dst + (l * 4 + h) * 128 + lane + 32);
                float d2 = __ldg(att_dst + (l * 4 + h) * 128 + lane + 64);
                float d3 = __ldg(att_dst + (l * 4 + h) * 128 + lane + 96);
                for (int row = w; row < 120; row += 8) {
                    const float h0 = S->hh[row][lane];
                    const float h1 = S->hh[row][lane + 32];
                    const float h2 = S->hh[row][lane + 64];
                    const float h3 = S->hh[row][lane + 96];
                    float as = h0 * s0 + h1 * s1 + h2 * s2 + h3 * s3;
                    float ad = h0 * d0 + h1 * d1 + h2 * d2 + h3 * d3;
                    #pragma unroll
                    for (int o = 16; o > 0; o >>= 1) {
                        as += __shfl_xor_sync(0xffffffffu, as, o);
                        ad += __shfl_xor_sync(0xffffffffu, ad, o);
                    }
                    if (lane == 0) { S->as[row] = as; S->ad[row] = ad; }
                }
            }
            __syncthreads();

            // ---- softmax over neighbors: 120 (tt,i) units ----
            if (t < 120) {
                const int tt = t / 10, i = t - tt * 10;
                const float adv = S->ad[t];
                const int cnt = c_nbr_cnt[i];
                float lg[5];
                float mx = -1e30f;
                for (int q = 0; q < cnt; q++) {
                    float v = adv + S->as[tt * 10 + c_nbr[i][q]];
                    v = (v >= 0.0f) ? v : 0.2f * v;
                    lg[q] = v;
                    mx = fmaxf(mx, v);
                }
                float sum = 0.0f;
                for (int q = 0; q < cnt; q++) { lg[q] = expf(lg[q] - mx); sum += lg[q]; }
                const float inv = 1.0f / sum;
                for (int q = 0; q < cnt; q++)
                    S->alpha[(tt * 10 + i) * 10 + c_nbr[i][q]] = lg[q] * inv;
            }
            __syncthreads();

            // ---- aggregation: outacc[tt*10+i][e] (+)= sum_j alpha*hh[tt*10+j][e] ----
            #pragma unroll
            for (int q = 0; q < 6; q++) {
                const int p = t + NT * q;
                const int tt = p >> 7;
                float hv[N_REGIONS];
                #pragma unroll
                for (int j = 0; j < N_REGIONS; j++) hv[j] = S->hh[tt * 10 + j][e];
                #pragma unroll
                for (int i = 0; i < N_REGIONS; i++) {
                    float s = 0.0f;
                    const int cnt = c_nbr_cnt[i];
                    for (int qn = 0; qn < cnt; qn++) {
                        const int j = c_nbr[i][qn];
                        s += S->alpha[(tt * 10 + i) * 10 + j] * hv[j];
                    }
                    if (h == 0) S->outacc[tt * 10 + i][e] = s;
                    else        S->outacc[tt * 10 + i][e] += s;
                }
            }
            __syncthreads();
        } // heads

        // ---- epilogue: mean heads + bias + GELU + residual ----
        {
            const float bg = b_gat[l * 128 + e];
            #pragma unroll
            for (int q = 0; q < 6; q++) {
                const int p = t + NT * q;
                const int tt = p >> 7;
                const int tok = tok0 + tt;
                #pragma unroll
                for (int i = 0; i < N_REGIONS; i++) {
                    const int row = tt * 10 + i;
                    const float v = S->outacc[row][e] * 0.25f + bg;
                    const float nn = gelu_exact(v) + S->nodes[row][e];
                    S->nodes[row][e] = nn;
                    if (l == N_LAYERS - 1 && tok < TOKENS)
                        out[(size_t)tok * 1280 + i * 128 + e] = nn;
                }
            }
        }
        __syncthreads();
    } // layers
}

extern "C" void kernel_launch(void* const* d_in, const int* in_sizes, int n_in,
                              void* d_out, int out_size) {
    (void)in_sizes; (void)n_in; (void)out_size;
    const float* x        = (const float*)d_in[0];
    const float* W_enc    = (const float*)d_in[1];
    const float* b_enc    = (const float*)d_in[2];
    const float* g_enc    = (const float*)d_in[3];
    const float* beta_enc = (const float*)d_in[4];
    const float* W_gat    = (const float*)d_in[5];
    const float* att_src  = (const float*)d_in[6];
    const float* att_dst  = (const float*)d_in[7];
    const float* b_gat    = (const float*)d_in[8];
    float* out = (float*)d_out;

    static_assert(sizeof(Smem) <= 227 * 1024, "smem overflow");
    cudaFuncSetAttribute(brain_mma_kernel,
                         cudaFuncAttributeMaxDynamicSharedMemorySize, (int)sizeof(Smem));

    wpack_kernel<<<(N_LAYERS * HEADS * 16 * 16 * 32) / 256, 256>>>(W_gat);
    brain_mma_kernel<<<NCTAS, NT, sizeof(Smem)>>>(
        x, W_enc, b_enc, g_enc, beta_enc, att_src, att_dst, b_gat, out);
}

// round 9
// speedup vs baseline: 2.1894x; 2.1894x over previous
#include <cuda_runtime.h>
#include <math.h>
#include <stdint.h>

#define N_REGIONS 10
#define HIDDEN    128
#define HEADS     4
#define N_LAYERS  3
#define CHPR      7
#define TOKENS    16384
#define TB        2            // tokens per block
#define NTHREADS  256
typedef unsigned long long u64;

__constant__ int c_nbr_cnt[N_REGIONS] = {5,5,5,3,3,4,3,4,2,2};
__constant__ int c_nbr[N_REGIONS][5] = {
    {0,1,2,3,4},{0,1,2,5,7},{0,1,2,3,7},{0,2,3,0,0},{0,4,5,0,0},
    {1,4,5,6,0},{5,6,9,0,0},{1,2,7,8,0},{7,8,0,0,0},{6,9,0,0,0}
};

// packed GAT weights: g_W4[(l*32+mm)*512 + col] = {W[4mm][col],W[4mm+1][col],W[4mm+2][col],W[4mm+3][col]}
__device__ uint4 g_W4[N_LAYERS * 32 * 512];

__device__ __forceinline__ float gelu_exact(float v) {
    return 0.5f * v * (1.0f + erff(v * 0.70710678118654752f));
}
__device__ __forceinline__ u64 ffma2(u64 a, u64 b, u64 c) {
    u64 d; asm("fma.rn.f32x2 %0, %1, %2, %3;" : "=l"(d) : "l"(a), "l"(b), "l"(c)); return d;
}
__device__ __forceinline__ float hadd2(u64 a) {
    float lo, hi; asm("mov.b64 {%0,%1}, %2;" : "=f"(lo), "=f"(hi) : "l"(a)); return lo + hi;
}

__global__ void wpack_kernel(const float* __restrict__ W) {
    const int idx = blockIdx.x * 256 + threadIdx.x;    // 0 .. 49151
    const int col = idx & 511;
    const int mm  = (idx >> 9) & 31;
    const int l   = idx >> 14;
    const size_t base = (size_t)l * 65536 + (size_t)(4 * mm) * 512 + col;
    uint4 v;
    v.x = __float_as_uint(W[base]);
    v.y = __float_as_uint(W[base + 512]);
    v.z = __float_as_uint(W[base + 1024]);
    v.w = __float_as_uint(W[base + 1536]);
    g_W4[idx] = v;
}

struct Smem {
    float nodes[TB][N_REGIONS][HIDDEN];           // 10 KB (rows 512B-aligned)
    float hh[TB][N_REGIONS][HEADS * HIDDEN];      // 40 KB
    float alpha[TB][N_REGIONS][N_REGIONS][HEADS]; // 3.2 KB
    float a[TB][N_REGIONS][HEADS][2];
    float x[TB][72];
    float mu[TB][N_REGIONS];
    float rstd[TB][N_REGIONS];
};

__global__ void __launch_bounds__(NTHREADS, 2) brain_graph_kernel(
    const float* __restrict__ x,
    const float* __restrict__ W_enc,
    const float* __restrict__ b_enc,
    const float* __restrict__ g_enc,
    const float* __restrict__ beta_enc,
    const float* __restrict__ att_src,
    const float* __restrict__ att_dst,
    const float* __restrict__ b_gat,
    float* __restrict__ out)
{
    extern __shared__ Smem S[];
    const int t    = threadIdx.x;        // 0..255
    const int wrp  = t >> 5;             // 0..7
    const int lane = t & 31;
    const int tok0 = blockIdx.x * TB;

    const int gt = t >> 7;               // token within block
    const int c  = t & 127;              // base column

    // ---- load token inputs ----
    if (t < TB * 70) {
        int tt = t / 70, ch = t - tt * 70;
        S->x[tt][ch] = x[(size_t)(tok0 + tt) * 70 + ch];
    }
    __syncthreads();

    // ---- encoders: Linear(7,128); one (gt,c) per thread ----
    {
        #pragma unroll
        for (int r = 0; r < N_REGIONS; r++) {
            float acc = b_enc[r * HIDDEN + c];
            #pragma unroll
            for (int ch = 0; ch < CHPR; ch++)
                acc += S->x[gt][r * CHPR + ch] * W_enc[(r * CHPR + ch) * HIDDEN + c];
            S->nodes[gt][r][c] = acc;
        }
    }
    __syncthreads();

    // ---- LayerNorm stats: 20 rows over 8 warps ----
    for (int rl = wrp; rl < TB * N_REGIONS; rl += 8) {
        const int tt = rl / N_REGIONS, r = rl - tt * N_REGIONS;
        float v0 = S->nodes[tt][r][lane];
        float v1 = S->nodes[tt][r][lane + 32];
        float v2 = S->nodes[tt][r][lane + 64];
        float v3 = S->nodes[tt][r][lane + 96];
        float s  = v0 + v1 + v2 + v3;
        float sq = v0*v0 + v1*v1 + v2*v2 + v3*v3;
        #pragma unroll
        for (int o = 16; o > 0; o >>= 1) {
            s  += __shfl_xor_sync(0xffffffffu, s,  o);
            sq += __shfl_xor_sync(0xffffffffu, sq, o);
        }
        if (lane == 0) {
            float mu  = s * (1.0f / HIDDEN);
            float var = sq * (1.0f / HIDDEN) - mu * mu;
            S->mu[tt][r]   = mu;
            S->rstd[tt][r] = rsqrtf(var + 1e-5f);
        }
    }
    __syncthreads();

    // ---- LN affine + GELU; write enc output ----
    {
        const size_t enc_base = (size_t)TOKENS * 1280 + (size_t)(tok0 + gt) * 1280;
        #pragma unroll
        for (int r = 0; r < N_REGIONS; r++) {
            float v = (S->nodes[gt][r][c] - S->mu[gt][r]) * S->rstd[gt][r]
                      * g_enc[r * HIDDEN + c] + beta_enc[r * HIDDEN + c];
            float g = gelu_exact(v);
            S->nodes[gt][r][c] = g;
            out[enc_base + r * HIDDEN + c] = g;
        }
    }
    __syncthreads();

    // ---- GAT layers ----
    for (int l = 0; l < N_LAYERS; l++) {
        // GEMM: hh[gt][r][col] = sum_k nodes[gt][r][k]*W[k][col]
        // thread: token gt, columns c + 128*p (p=0..3); prefetched uint4 weights (4 k per col)
        {
            const uint4* __restrict__ Wb = g_W4 + (size_t)l * 32 * 512 + c;
            u64 acc[N_REGIONS][4];
            #pragma unroll
            for (int r = 0; r < N_REGIONS; r++)
                #pragma unroll
                for (int p = 0; p < 4; p++) acc[r][p] = 0ull;

            uint4 wc[4];
            #pragma unroll
            for (int p = 0; p < 4; p++) wc[p] = __ldg(Wb + 128 * p);

            #pragma unroll 1
            for (int mm = 0; mm < 32; mm++) {
                // prefetch next iteration's weights (last iter reloads mm=31; harmless)
                uint4 wn[4];
                {
                    const int nmm = (mm < 31) ? mm + 1 : 31;
                    #pragma unroll
                    for (int p = 0; p < 4; p++)
                        wn[p] = __ldg(Wb + (size_t)nmm * 512 + 128 * p);
                }
                #pragma unroll
                for (int r = 0; r < N_REGIONS; r++) {
                    const ulonglong2 nd =
                        *reinterpret_cast<const ulonglong2*>(&S->nodes[gt][r][4 * mm]);
                    #pragma unroll
                    for (int p = 0; p < 4; p++) {
                        const ulonglong2 wv = *reinterpret_cast<const ulonglong2*>(&wc[p]);
                        acc[r][p] = ffma2(nd.x, wv.x, acc[r][p]);
                        acc[r][p] = ffma2(nd.y, wv.y, acc[r][p]);
                    }
                }
                #pragma unroll
                for (int p = 0; p < 4; p++) wc[p] = wn[p];
            }
            #pragma unroll
            for (int r = 0; r < N_REGIONS; r++)
                #pragma unroll
                for (int p = 0; p < 4; p++)
                    S->hh[gt][r][c + 128 * p] = hadd2(acc[r][p]);
        }
        __syncthreads();

        // attention scores: TB*80 = 160 length-128 dots over 8 warps
        for (int d = wrp; d < TB * N_REGIONS * HEADS * 2; d += 8) {
            const int tt  = d / 80;
            const int rem = d - tt * 80;
            const int n   = rem >> 3;
            const int h   = (rem >> 1) & 3;
            const int sd  = rem & 1;
            const float* att = (sd ? att_dst : att_src) + l * (HEADS * HIDDEN) + h * HIDDEN;
            float p = 0.0f;
            #pragma unroll
            for (int e = 0; e < HIDDEN; e += 32)
                p += S->hh[tt][n][h * HIDDEN + e + lane] * att[e + lane];
            #pragma unroll
            for (int o = 16; o > 0; o >>= 1)
                p += __shfl_xor_sync(0xffffffffu, p, o);
            if (lane == 0) S->a[tt][n][h][sd] = p;
        }
        __syncthreads();

        // softmax over neighbors: 80 (tt,i,h) units
        if (t < TB * N_REGIONS * HEADS) {
            const int tt  = t / 40;
            const int rem = t - tt * 40;
            const int i = rem >> 2, h = rem & 3;
            const int cnt = c_nbr_cnt[i];
            const float ad = S->a[tt][i][h][1];
            float lg[5];
            float mx = -1e30f;
            for (int q = 0; q < cnt; q++) {
                const int j = c_nbr[i][q];
                float v = ad + S->a[tt][j][h][0];
                v = (v >= 0.0f) ? v : 0.2f * v;
                lg[q] = v;
                mx = fmaxf(mx, v);
            }
            float sum = 0.0f;
            for (int q = 0; q < cnt; q++) { lg[q] = expf(lg[q] - mx); sum += lg[q]; }
            const float inv = 1.0f / sum;
            for (int q = 0; q < cnt; q++)
                S->alpha[tt][i][c_nbr[i][q]][h] = lg[q] * inv;
        }
        __syncthreads();

        // aggregate + mean heads + bias + GELU + residual: thread owns (gt, c)
        {
            const float bg = b_gat[l * HIDDEN + c];
            #pragma unroll
            for (int i = 0; i < N_REGIONS; i++) {
                float acc = 0.0f;
                const int cnt = c_nbr_cnt[i];
                for (int q = 0; q < cnt; q++) {
                    const int j = c_nbr[i][q];
                    #pragma unroll
                    for (int h = 0; h < HEADS; h++)
                        acc += S->alpha[gt][i][j][h] * S->hh[gt][j][h * HIDDEN + c];
                }
                float v = acc * 0.25f + bg;
                S->nodes[gt][i][c] = gelu_exact(v) + S->nodes[gt][i][c];
            }
        }
        __syncthreads();
    }

    // ---- graph_features output ----
    {
        const size_t gf_base = (size_t)(tok0 + gt) * 1280;
        #pragma unroll
        for (int i = 0; i < N_REGIONS; i++)
            out[gf_base + i * HIDDEN + c] = S->nodes[gt][i][c];
    }
}

extern "C" void kernel_launch(void* const* d_in, const int* in_sizes, int n_in,
                              void* d_out, int out_size) {
    (void)in_sizes; (void)n_in; (void)out_size;
    const float* x        = (const float*)d_in[0];
    const float* W_enc    = (const float*)d_in[1];
    const float* b_enc    = (const float*)d_in[2];
    const float* g_enc    = (const float*)d_in[3];
    const float* beta_enc = (const float*)d_in[4];
    const float* W_gat    = (const float*)d_in[5];
    const float* att_src  = (const float*)d_in[6];
    const float* att_dst  = (const float*)d_in[7];
    const float* b_gat    = (const float*)d_in[8];
    float* out = (float*)d_out;

    static_assert(sizeof(Smem) < 57 * 1024, "smem too big for 2 blocks/SM");
    cudaFuncSetAttribute(brain_graph_kernel,
                         cudaFuncAttributeMaxDynamicSharedMemorySize, (int)sizeof(Smem));

    wpack_kernel<<<(N_LAYERS * 32 * 512) / 256, 256>>>(W_gat);
    brain_graph_kernel<<<TOKENS / TB, NTHREADS, sizeof(Smem)>>>(
        x, W_enc, b_enc, g_enc, beta_enc, att_src, att_dst, b_gat, out);
}